// round 17
// baseline (speedup 1.0000x reference)
#include <cuda_runtime.h>
#include <math.h>
#include <float.h>
#include <stdint.h>

#define N_LOC 16384   // H*W
#define C_DIM 256
#define N_SRC 12288   // unmasked sources (packed)
#define ASTR 136      // A smem row stride (u32): conflict-free frag loads
#define BSTR 36       // B smem row stride (u32): conflict-free frag loads
#define A_SZ 4352     // 32 kpair rows * 136
#define BUFU 8960     // A_SZ + 128*36
#define BH0  524288   // u32 offset of Bh plane in out (channel rows 32..127)

typedef unsigned long long ull;

// ---- scratch inside d_out (all regions audited disjoint; all erased or
//      overwritten by scatter_win + final_copy) ------------------------------
// cand: rows 0..31 col<4096, rows 128..255 col<4096, rows 0..31 col 12288+
// inv:  rows 128..130 col 12288+
// Ah:   rows 131..254 col 12288+ and rows 0..1 col 4096..12287
// Bh:   rows 32..127 full width
// qT:   rows 128..255 col 4096..12287 (exact fp32 queries; read by rescore,
//       clobbered only afterwards by scatter_win's masked-column writes)
__device__ __forceinline__ size_t cand_off(int i) {
    int sl = i >> 12, c = i & 4095;
    if (sl < 160) return ((size_t)(sl < 32 ? sl : sl + 96) << 14) + c;
    return ((size_t)(sl - 160) << 14) + 12288 + c;
}
__device__ __forceinline__ size_t inv_off(int j) {
    return ((size_t)(128 + (j >> 12)) << 14) + 12288 + (j & 4095);
}
__device__ __forceinline__ size_t ah_off(size_t i) {
    if (i < 507904) return ((size_t)(131 + (i >> 12)) << 14) + 12288 + (i & 4095);
    size_t j = i - 507904;
    return ((j >> 13) << 14) + 4096 + (j & 8191);
}
__device__ __forceinline__ size_t best_off(int m) { return ah_off((size_t)m); }
__device__ __forceinline__ size_t qt_off(size_t idx) {   // idx = m*256 + c
    return ((size_t)(128 + (idx >> 13)) << 14) + 4096 + (idx & 8191);
}
// packed source index -> raw location (strictly increasing => ties preserved)
__device__ __forceinline__ int src_q(int j) {
    if (j < 4096) return j;
    if (j < 8192) {
        int r = (j - 4096) >> 6, c = (j - 4096) & 63;
        return (32 + r) * 128 + (c < 32 ? c : c + 64);
    }
    return j + 4096;
}
__device__ __forceinline__ unsigned packc(float v, int sp) {
    unsigned u = __float_as_uint(v);
    u = (u & 0x80000000u) ? ~u : (u | 0x80000000u);   // orderable
    return (u & 0xFFFFC000u) | (unsigned)sp;          // 18b value | 14b idx
}
__device__ __forceinline__ float unordf(unsigned u) {
    u = (u & 0x80000000u) ? (u & 0x7FFFFFFFu) : ~u;
    return __uint_as_float(u);
}
__device__ __forceinline__ uint32_t smem_u32(const void* p) {
    uint32_t a;
    asm("{ .reg .u64 t; cvta.to.shared.u64 t, %1; cvt.u32.u64 %0, t; }"
        : "=r"(a) : "l"(p));
    return a;
}
__device__ __forceinline__ unsigned pk16(float hi_, float lo_) {
    unsigned r;
    asm("cvt.rn.f16x2.f32 %0, %1, %2;" : "=r"(r) : "f"(hi_), "f"(lo_));
    return r;
}

#define MMAH(C, x0, x1, x2, x3, y0, y1)                                      \
    asm volatile(                                                            \
        "mma.sync.aligned.m16n8k16.row.col.f32.f16.f16.f32 "                 \
        "{%0,%1,%2,%3},{%4,%5,%6,%7},{%8,%9},{%0,%1,%2,%3};"                 \
        : "+f"(C.x), "+f"(C.y), "+f"(C.z), "+f"(C.w)                         \
        : "r"(x0), "r"(x1), "r"(x2), "r"(x3), "r"(y0), "r"(y1));

#define CP16(DST, SRC)                                                       \
    asm volatile("cp.async.ca.shared.global [%0], [%1], 16;"                 \
                 :: "r"(DST), "l"(SRC) : "memory")
#define CP_COMMIT() asm volatile("cp.async.commit_group;" ::: "memory")
#define CP_WAIT1()  asm volatile("cp.async.wait_group 1;" ::: "memory")
#define CP_WAIT0()  asm volatile("cp.async.wait_group 0;" ::: "memory")

// ---------------------------------------------------------------------------
// 1a. prep_split (2 threads/source): inv -> inv plane; Bh = f16(x*inv).
// ---------------------------------------------------------------------------
__global__ void prep_split(const float* __restrict__ x, float* out) {
    __shared__ float ssum[2][128];
    __shared__ float sinv[128];
    int t = threadIdx.x;
    int jl = t & 127, h = t >> 7;
    int j = blockIdx.x * 128 + jl;
    int q = src_q(j);
    float sum = 0.f;
#pragma unroll 8
    for (int ci = 0; ci < 128; ci++) {
        float v = x[(size_t)(h * 128 + ci) * N_LOC + q];
        sum = fmaf(v, v, sum);
    }
    ssum[h][jl] = sum;
    __syncthreads();
    uint32_t* ou = (uint32_t*)out;
    if (t < 128) {
        float inv = 1.0f / (sqrtf(ssum[0][t] + ssum[1][t]) + 1e-8f);
        sinv[t] = inv;
        ou[inv_off(blockIdx.x * 128 + t)] = __float_as_uint(inv);
    }
    __syncthreads();
    float inv = sinv[jl];
    uint32_t* bh = ou + BH0 + (size_t)j * 128 + h * 64;
#pragma unroll 4
    for (int w = 0; w < 64; w++) {
        int wc = h * 64 + w;
        float v0 = x[(size_t)(2 * wc) * N_LOC + q] * inv;
        float v1 = x[(size_t)(2 * wc + 1) * N_LOC + q] * inv;
        bh[w] = pk16(v1, v0);
    }
}

// ---------------------------------------------------------------------------
// 1b. prep_a: masked-query f16 plane Ah[w][m] (k-major) + exact fp32 qT plane.
// ---------------------------------------------------------------------------
__global__ void prep_a(const float* __restrict__ x, float* out) {
    int m = blockIdx.x * 128 + threadIdx.x;   // 4096 threads
    int q = (32 + (m >> 6)) * 128 + 32 + (m & 63);
    uint32_t* ou = (uint32_t*)out;
#pragma unroll 4
    for (int w = 0; w < 128; w++) {
        float v0 = x[(size_t)(2 * w) * N_LOC + q];
        float v1 = x[(size_t)(2 * w + 1) * N_LOC + q];
        ou[ah_off((size_t)w * 4096 + m)] = pk16(v1, v0);
        out[qt_off((size_t)m * 256 + 2 * w)]     = v0;
        out[qt_off((size_t)m * 256 + 2 * w + 1)] = v1;
    }
}

// ---------------------------------------------------------------------------
// 2. 1-term fp16 screening GEMM, k-chunk 64 (4 chunks), prepacked A+B.
//    CTA = 128q x 128s, 8 warps = 8m x 1n; force 2 CTAs/SM (live regs ~100).
// ---------------------------------------------------------------------------
__global__ void __launch_bounds__(256, 2)
gemm_screen(float* out) {
    extern __shared__ __align__(16) uint32_t smemu[];
    const int tid = threadIdx.x;
    const int warp = tid >> 5, lane = tid & 31;
    const int gid = lane >> 2, tig = lane & 3;
    const int my = warp * 16;
    const int sb = blockIdx.x * 128;        // packed source base
    const int qb = blockIdx.y * 128;        // masked-query base
    const uint32_t sbase = smem_u32(smemu);
    const uint32_t* outu = (const uint32_t*)out;

#define STAGE(PH, CH)                                                        \
    {                                                                        \
        const int base = (PH) * BUFU;                                        \
        _Pragma("unroll")                                                    \
        for (int i = 0; i < 4; i++) {          /* A: 32 kpair x 128 m */     \
            int u = i * 256 + tid;                                           \
            int r = u >> 5;                                                  \
            int m4 = (u & 31) << 2;                                          \
            size_t ai = (size_t)((CH) * 32 + r) * 4096 + qb + m4;            \
            CP16(sbase + (uint32_t)(base + r * ASTR + m4) * 4u,              \
                 outu + ah_off(ai));                                         \
        }                                                                    \
        _Pragma("unroll")                                                    \
        for (int i = 0; i < 4; i++) {          /* B: 128 col x 32 kpair */   \
            int u = i * 256 + tid;                                           \
            int col = u >> 3;                                                \
            int h4 = (u & 7) << 2;                                           \
            CP16(sbase + (uint32_t)(base + A_SZ + col * BSTR + h4) * 4u,     \
                 outu + BH0 + (size_t)(sb + col) * 128 + (CH) * 32 + h4);    \
        }                                                                    \
        CP_COMMIT();                                                         \
    }

    const float4 z4 = make_float4(0.f, 0.f, 0.f, 0.f);
    float4 c0 = z4, c1 = z4, c2 = z4, c3 = z4, c4 = z4, c5 = z4, c6 = z4, c7 = z4;
    float4 c8 = z4, c9 = z4, c10 = z4, c11 = z4, c12 = z4, c13 = z4, c14 = z4, c15 = z4;

    STAGE(0, 0)

    for (int cc = 0; cc < 4; cc++) {
        if (cc < 3) {
            STAGE((cc + 1) & 1, cc + 1)
            CP_WAIT1();
        } else {
            CP_WAIT0();
        }
        __syncthreads();

        const uint32_t* As = smemu + (cc & 1) * BUFU;
        const uint32_t* Bs = As + A_SZ;
#pragma unroll
        for (int ks = 0; ks < 4; ks++) {
            const int kp0 = (ks * 8 + tig) * ASTR;
            const int kp1 = (ks * 8 + 4 + tig) * ASTR;
            unsigned ah0 = As[kp0 + my + gid];
            unsigned ah1 = As[kp0 + my + 8 + gid];
            unsigned ah2 = As[kp1 + my + gid];
            unsigned ah3 = As[kp1 + my + 8 + gid];
            const int ksw = ks * 8;

#define LDB(J, S)                                                            \
            const uint32_t* _p##S = Bs + (unsigned)((J) * 8 + gid) * BSTR + ksw; \
            unsigned b0_##S = _p##S[tig], b1_##S = _p##S[4 + tig];
#define DO4(JA, JB, JC, JD, CA, CB, CC_, CD)                                 \
            {                                                                \
                LDB(JA, 0) LDB(JB, 1) LDB(JC, 2) LDB(JD, 3)                  \
                MMAH(CA,  ah0, ah1, ah2, ah3, b0_0, b1_0)                    \
                MMAH(CB,  ah0, ah1, ah2, ah3, b0_1, b1_1)                    \
                MMAH(CC_, ah0, ah1, ah2, ah3, b0_2, b1_2)                    \
                MMAH(CD,  ah0, ah1, ah2, ah3, b0_3, b1_3)                    \
            }
            DO4(0, 1, 2, 3,     c0,  c1,  c2,  c3)
            DO4(4, 5, 6, 7,     c4,  c5,  c6,  c7)
            DO4(8, 9, 10, 11,   c8,  c9,  c10, c11)
            DO4(12, 13, 14, 15, c12, c13, c14, c15)
#undef DO4
#undef LDB
        }
        __syncthreads();
    }
#undef STAGE

    // ---- epilogue: per-row top-2 over 128 cols, store packed candidates ---
    uint32_t* ow = (uint32_t*)out;
#define INSV(V, I)                                                           \
    { float _v = (V); int _i = (I);                                          \
      if (_v > v1) { v2 = v1; i2 = i1; v1 = _v; i1 = _i; }                   \
      else if (_v > v2) { v2 = _v; i2 = _i; } }
#define MERGE(OFF)                                                           \
    { float ov1 = __shfl_xor_sync(0xffffffffu, v1, OFF);                     \
      int   oi1 = __shfl_xor_sync(0xffffffffu, i1, OFF);                     \
      float ov2 = __shfl_xor_sync(0xffffffffu, v2, OFF);                     \
      int   oi2 = __shfl_xor_sync(0xffffffffu, i2, OFF);                     \
      INSV(ov1, oi1) INSV(ov2, oi2) }
#define RX(CJ, J) INSV(CJ.x, (J) * 8 + tig * 2) INSV(CJ.y, (J) * 8 + tig * 2 + 1)
#define RZ(CJ, J) INSV(CJ.z, (J) * 8 + tig * 2) INSV(CJ.w, (J) * 8 + tig * 2 + 1)
    {
        float v1 = -FLT_MAX, v2 = -FLT_MAX; int i1 = 0, i2 = 1;
        RX(c0,0) RX(c1,1) RX(c2,2) RX(c3,3) RX(c4,4) RX(c5,5) RX(c6,6) RX(c7,7)
        RX(c8,8) RX(c9,9) RX(c10,10) RX(c11,11) RX(c12,12) RX(c13,13) RX(c14,14) RX(c15,15)
        MERGE(1) MERGE(2)
        if (tig == 0) {
            int m = qb + my + gid;
            int ib = (m * 96 + blockIdx.x) * 2;
            ow[cand_off(ib)]     = packc(v1, sb + i1);
            ow[cand_off(ib + 1)] = packc(v2, sb + i2);
        }
    }
    {
        float v1 = -FLT_MAX, v2 = -FLT_MAX; int i1 = 0, i2 = 1;
        RZ(c0,0) RZ(c1,1) RZ(c2,2) RZ(c3,3) RZ(c4,4) RZ(c5,5) RZ(c6,6) RZ(c7,7)
        RZ(c8,8) RZ(c9,9) RZ(c10,10) RZ(c11,11) RZ(c12,12) RZ(c13,13) RZ(c14,14) RZ(c15,15)
        MERGE(1) MERGE(2)
        if (tig == 0) {
            int m = qb + my + 8 + gid;
            int ib = (m * 96 + blockIdx.x) * 2;
            ow[cand_off(ib)]     = packc(v1, sb + i1);
            ow[cand_off(ib + 1)] = packc(v2, sb + i2);
        }
    }
#undef RX
#undef RZ
#undef MERGE
#undef INSV
}

// ---------------------------------------------------------------------------
// 3. rescore: 1 warp per masked query; warp-cooperative exact fp32 rescore.
//    Query side reads the COALESCED qT plane (identical values/order).
// ---------------------------------------------------------------------------
__global__ void rescore(const float* __restrict__ x, float* out) {
    int m = (blockIdx.x * 256 + threadIdx.x) >> 5;    // 0..4095
    int lane = threadIdx.x & 31;
    const uint32_t* ou = (const uint32_t*)out;

    unsigned pmax = 0;
#pragma unroll
    for (int it = 0; it < 6; it++) {
        unsigned p = ou[cand_off(m * 192 + it * 32 + lane)];
        if (p > pmax) pmax = p;
    }
#pragma unroll
    for (int off = 16; off >= 1; off >>= 1) {
        unsigned o = __shfl_xor_sync(0xffffffffu, pmax, off);
        if (o > pmax) pmax = o;
    }
    float thr = unordf(pmax & 0xFFFFC000u) - 0.08f;

    // preload this query's channels (coalesced; exact fp32 copies of x[:,q])
    float qv0 = out[qt_off((size_t)m * 256 + 0 * 32 + lane)];
    float qv1 = out[qt_off((size_t)m * 256 + 1 * 32 + lane)];
    float qv2 = out[qt_off((size_t)m * 256 + 2 * 32 + lane)];
    float qv3 = out[qt_off((size_t)m * 256 + 3 * 32 + lane)];
    float qv4 = out[qt_off((size_t)m * 256 + 4 * 32 + lane)];
    float qv5 = out[qt_off((size_t)m * 256 + 5 * 32 + lane)];
    float qv6 = out[qt_off((size_t)m * 256 + 6 * 32 + lane)];
    float qv7 = out[qt_off((size_t)m * 256 + 7 * 32 + lane)];

    float bv = -FLT_MAX;
    int bs = 0x7FFFFFFF;
#pragma unroll 1
    for (int it = 0; it < 6; it++) {
        unsigned p = ou[cand_off(m * 192 + it * 32 + lane)];
        bool act = unordf(p & 0xFFFFC000u) >= thr;
        unsigned bal = __ballot_sync(0xffffffffu, act);
        while (bal) {
            int src = __ffs(bal) - 1;
            bal &= bal - 1;
            int sp = __shfl_sync(0xffffffffu, (int)(p & 0x3FFF), src);
            int sr = src_q(sp);
            float part = 0.f;
            part = fmaf(qv0, x[(size_t)(0 * 32 + lane) * N_LOC + sr], part);
            part = fmaf(qv1, x[(size_t)(1 * 32 + lane) * N_LOC + sr], part);
            part = fmaf(qv2, x[(size_t)(2 * 32 + lane) * N_LOC + sr], part);
            part = fmaf(qv3, x[(size_t)(3 * 32 + lane) * N_LOC + sr], part);
            part = fmaf(qv4, x[(size_t)(4 * 32 + lane) * N_LOC + sr], part);
            part = fmaf(qv5, x[(size_t)(5 * 32 + lane) * N_LOC + sr], part);
            part = fmaf(qv6, x[(size_t)(6 * 32 + lane) * N_LOC + sr], part);
            part = fmaf(qv7, x[(size_t)(7 * 32 + lane) * N_LOC + sr], part);
#pragma unroll
            for (int off = 16; off >= 1; off >>= 1)
                part += __shfl_xor_sync(0xffffffffu, part, off);
            float val = part * __uint_as_float(ou[inv_off(sp)]);
            if (val > bv || (val == bv && sr < bs)) { bv = val; bs = sr; }
        }
    }
    if (lane == 0) ((uint32_t*)out)[best_off(m)] = (unsigned)bs;
}

// ---------------------------------------------------------------------------
// 3b. scatter_win: coalesced winner-column scatter (lanes = consecutive q).
// ---------------------------------------------------------------------------
__global__ void scatter_win(const float* __restrict__ x, float* out) {
    int w = threadIdx.x >> 5, lane = threadIdx.x & 31;
    int m = blockIdx.x * 32 + lane;                   // grid 128 x 256
    int s = (int)((const uint32_t*)out)[best_off(m)];
    int q = (32 + (m >> 6)) * 128 + 32 + (m & 63);
#pragma unroll
    for (int i = 0; i < 32; i++) {
        int c = w * 32 + i;
        out[(size_t)c * N_LOC + q] = x[(size_t)c * N_LOC + s];
    }
}

// ---------------------------------------------------------------------------
// 4. Final copy: out = x at unmasked cells only (also erases all scratch).
// ---------------------------------------------------------------------------
__global__ void final_copy(const float4* __restrict__ x4,
                           const int4* __restrict__ mask4, float4* o4) {
    int i = blockIdx.x * blockDim.x + threadIdx.x;
    int qq = i & (N_LOC / 4 - 1);
    int4 mk = mask4[qq];
    float4 v = x4[i];
    if ((mk.x | mk.y | mk.z | mk.w) == 0) {
        o4[i] = v;
    } else {
        float* o = (float*)(o4 + i);
        if (!mk.x) o[0] = v.x;
        if (!mk.y) o[1] = v.y;
        if (!mk.z) o[2] = v.z;
        if (!mk.w) o[3] = v.w;
    }
}

// ---------------------------------------------------------------------------
extern "C" void kernel_launch(void* const* d_in, const int* in_sizes, int n_in,
                              void* d_out, int out_size) {
    const float* x;
    const int* mask;
    if (in_sizes[0] == N_LOC) {
        mask = (const int*)d_in[0];
        x    = (const float*)d_in[1];
    } else {
        x    = (const float*)d_in[0];
        mask = (const int*)d_in[1];
    }
    float* out = (float*)d_out;

    const int smem_bytes = 2 * BUFU * 4;   // 71,680 B
    static int smem_set = 0;
    if (!smem_set) {
        cudaFuncSetAttribute(gemm_screen,
                             cudaFuncAttributeMaxDynamicSharedMemorySize,
                             smem_bytes);
        smem_set = 1;
    }

    prep_split<<<N_SRC / 128, 256>>>(x, out);
    prep_a<<<4096 / 128, 128>>>(x, out);
    gemm_screen<<<dim3(N_SRC / 128, 32), 256, smem_bytes>>>(out);
    rescore<<<512, 256>>>(x, out);
    scatter_win<<<128, 256>>>(x, out);
    final_copy<<<(N_LOC * C_DIM / 4) / 256, 256>>>(
        (const float4*)x, (const int4*)mask, (float4*)out);
}